// round 5
// baseline (speedup 1.0000x reference)
#include <cuda_runtime.h>
#include <cstdint>

#define Zdim 41
#define Ydim 1024
#define Xdim 1024
#define NVOX (Zdim * Ydim * Xdim)      // 42,991,616
#define NWORDS (NVOX / 32)             // 1,343,488
#define C_IN 32
#define C_OUT 64
#define KVOL 27
#define KCENTER 13
#define MAXN 300000

// Dense index grid: validity gated by g_bitmap (wiped each launch); the grid
// itself is never cleared, stale entries are never read.
__device__ int      g_grid[NVOX];
__device__ unsigned g_bitmap[NWORDS];
__device__ int      g_npairs;
__device__ int2     g_pairs[MAXN * 8];   // (i<<5|k, nb); ~54k expected

__global__ void clear_bitmap_kernel() {
    int i = blockIdx.x * blockDim.x + threadIdx.x;
    if (i == 0) g_npairs = 0;
    if (i * 4 < NWORDS) ((uint4*)g_bitmap)[i] = make_uint4(0, 0, 0, 0);
}

__global__ void scatter_kernel(const int* __restrict__ idx, int n) {
    int i = blockIdx.x * blockDim.x + threadIdx.x;
    if (i >= n) return;
    int4 v = ((const int4*)idx)[i];
    unsigned lin = (unsigned)v.y * (Ydim * Xdim) + (unsigned)v.z * Xdim + (unsigned)v.w;
    g_grid[lin] = i;
    atomicOr(&g_bitmap[lin >> 5], 1u << (lin & 31));
}

__device__ __forceinline__ void fma2(unsigned long long& acc, float f,
                                     unsigned long long wv) {
    unsigned long long fv2;
    asm("mov.b64 %0, {%1, %1};" : "=l"(fv2) : "f"(f));
    asm("fma.rn.f32x2 %0, %1, %2, %3;" : "=l"(acc) : "l"(fv2), "l"(wv), "l"(acc));
}

// Main kernel: one warp per point (persistent).
//  - center matvec with WEIGHTS IN REGISTERS (zero memory ops for weights),
//    feature row read as broadcast LDG.128 (1 wavefront each, L1-hot line)
//  - neighbor probing fused in: probes issued BEFORE the FFMA chain so the
//    L2 bitmap round-trip hides under compute; hits warp-aggregated into
//    the pair list.
__global__ void __launch_bounds__(256) main_kernel(
    const float* __restrict__ feat,
    const int*   __restrict__ idx,
    const float* __restrict__ w,
    float* __restrict__ out,
    int n)
{
    int lane   = threadIdx.x & 31;
    int warp_g = (blockIdx.x * blockDim.x + threadIdx.x) >> 5;
    int nwarps = (gridDim.x * blockDim.x) >> 5;

    // Per-lane center weights: wreg[cin] = (w13[cin][lane], w13[cin][lane+32])
    const float* w13 = w + KCENTER * C_IN * C_OUT;
    unsigned long long wreg[C_IN];
    #pragma unroll
    for (int c = 0; c < C_IN; ++c) {
        float a = w13[c * C_OUT + lane];          // coalesced
        float b = w13[c * C_OUT + lane + 32];
        asm("mov.b64 %0, {%1, %2};" : "=l"(wreg[c]) : "f"(a), "f"(b));
    }

    int dz = lane / 9 - 1;
    int dy = (lane / 3) % 3 - 1;
    int dx = lane % 3 - 1;
    bool probe_lane = (lane < KVOL) && (lane != KCENTER);

    for (int i = warp_g; i < n; i += nwarps) {
        int4 v = ((const int4*)idx)[i];           // broadcast, 1 wavefront

        // ---- issue neighbor probes first (latency hides under FFMA) ----
        int nb = -1;
        if (probe_lane) {
            int nz = v.y + dz, ny = v.z + dy, nx = v.w + dx;
            if ((unsigned)nz < Zdim && (unsigned)ny < Ydim && (unsigned)nx < Xdim) {
                unsigned lin = (unsigned)nz * (Ydim * Xdim) + (unsigned)ny * Xdim + (unsigned)nx;
                if ((g_bitmap[lin >> 5] >> (lin & 31)) & 1u)
                    nb = g_grid[lin];             // rare (~0.7% of probes)
            }
        }

        // ---- center matvec: broadcast feature loads, register weights ----
        const float4* frow = (const float4*)(feat + (size_t)i * C_IN);
        unsigned long long acc0, acc1;
        asm("mov.b64 %0, {%1, %1};" : "=l"(acc0) : "f"(0.0f));
        asm("mov.b64 %0, {%1, %1};" : "=l"(acc1) : "f"(0.0f));
        #pragma unroll
        for (int c4 = 0; c4 < C_IN / 4; ++c4) {
            float4 fv = frow[c4];                 // all lanes same addr
            fma2(acc0, fv.x, wreg[c4 * 4 + 0]);
            fma2(acc1, fv.y, wreg[c4 * 4 + 1]);
            fma2(acc0, fv.z, wreg[c4 * 4 + 2]);
            fma2(acc1, fv.w, wreg[c4 * 4 + 3]);
        }
        float a0, a1, b0, b1;
        asm("mov.b64 {%0, %1}, %2;" : "=f"(a0), "=f"(a1) : "l"(acc0));
        asm("mov.b64 {%0, %1}, %2;" : "=f"(b0), "=f"(b1) : "l"(acc1));
        out[(size_t)i * C_OUT + lane]      = a0 + b0;
        out[(size_t)i * C_OUT + lane + 32] = a1 + b1;

        // ---- warp-aggregated pair append ----
        unsigned act = __ballot_sync(0xffffffffu, nb >= 0);
        if (act) {
            int base;
            if (lane == 0) base = atomicAdd(&g_npairs, __popc(act));
            base = __shfl_sync(0xffffffffu, base, 0);
            if (nb >= 0) {
                int r = __popc(act & ((1u << lane) - 1));
                g_pairs[base + r] = make_int2((i << 5) | lane, nb);
            }
        }
    }
}

// Rare neighbor contributions: persistent warps over the pair list,
// atomicAdd on top of the center result (separate launch: ordering vs
// main_kernel's plain stores).
__global__ void __launch_bounds__(256) pairs_kernel(
    const float* __restrict__ feat,
    const float* __restrict__ w,
    float* __restrict__ out)
{
    int lane   = threadIdx.x & 31;
    int warp_g = (blockIdx.x * blockDim.x + threadIdx.x) >> 5;
    int nwarps = (gridDim.x * blockDim.x) >> 5;
    int np = g_npairs;

    for (int p = warp_g; p < np; p += nwarps) {
        int2 pr = g_pairs[p];
        int i  = pr.x >> 5;
        int k  = pr.x & 31;
        int nb = pr.y;

        float f = feat[(size_t)nb * C_IN + lane];   // coalesced row
        const float* wk = w + (size_t)k * C_IN * C_OUT;

        float a0 = 0.0f, a1 = 0.0f;
        #pragma unroll
        for (int c = 0; c < C_IN; ++c) {
            float fv = __shfl_sync(0xffffffffu, f, c);
            a0 += fv * wk[c * C_OUT + lane];
            a1 += fv * wk[c * C_OUT + lane + 32];
        }
        atomicAdd(&out[(size_t)i * C_OUT + lane],      a0);
        atomicAdd(&out[(size_t)i * C_OUT + lane + 32], a1);
    }
}

extern "C" void kernel_launch(void* const* d_in, const int* in_sizes, int n_in,
                              void* d_out, int out_size) {
    const float* feat = (const float*)d_in[0];
    const int*   idx  = (const int*)d_in[1];
    const float* w    = (const float*)d_in[2];
    float* out = (float*)d_out;

    int n = in_sizes[0] / C_IN;

    clear_bitmap_kernel<<<(NWORDS / 4 + 255) / 256, 256>>>();
    scatter_kernel<<<(n + 255) / 256, 256>>>(idx, n);
    main_kernel<<<1184, 256>>>(feat, idx, w, out, n);
    pairs_kernel<<<592, 256>>>(feat, w, out);
}

// round 6
// speedup vs baseline: 1.2331x; 1.2331x over previous
#include <cuda_runtime.h>
#include <cstdint>

#define Zdim 41
#define Ydim 1024
#define Xdim 1024
#define NVOX (Zdim * Ydim * Xdim)      // 42,991,616
#define NWORDS (NVOX / 32)             // 1,343,488
#define C_IN 32
#define C_OUT 64
#define KVOL 27
#define KCENTER 13
#define MAXN 300000

// Dense index grid: validity gated by g_bitmap (wiped each launch); the grid
// itself is never cleared, so stale entries are never read.
__device__ int      g_grid[NVOX];
__device__ unsigned g_bitmap[NWORDS];
__device__ int      g_npairs;
__device__ int2     g_pairs[MAXN * 8];   // (i<<5|k, nb); ~54k expected

__global__ void clear_bitmap_kernel() {
    int i = blockIdx.x * blockDim.x + threadIdx.x;
    if (i == 0) g_npairs = 0;
    if (i * 4 < NWORDS) ((uint4*)g_bitmap)[i] = make_uint4(0, 0, 0, 0);
}

__global__ void scatter_kernel(const int* __restrict__ idx, int n) {
    int i = blockIdx.x * blockDim.x + threadIdx.x;
    if (i >= n) return;
    int4 v = ((const int4*)idx)[i];
    unsigned lin = (unsigned)v.y * (Ydim * Xdim) + (unsigned)v.z * Xdim + (unsigned)v.w;
    g_grid[lin] = i;
    atomicOr(&g_bitmap[lin >> 5], 1u << (lin & 31));
}

// One thread per (point, offset): fully parallel probing, no chains.
__global__ void probe_kernel(const int* __restrict__ idx, int n) {
    int t = blockIdx.x * blockDim.x + threadIdx.x;
    if (t >= n * KVOL) return;
    int i = t / KVOL;
    int k = t - i * KVOL;
    if (k == KCENTER) return;
    int4 v = ((const int4*)idx)[i];            // shared by 27 adjacent threads
    int nz = v.y + k / 9 - 1;
    int ny = v.z + (k / 3) % 3 - 1;
    int nx = v.w + k % 3 - 1;
    if ((unsigned)nz >= Zdim || (unsigned)ny >= Ydim || (unsigned)nx >= Xdim) return;
    unsigned lin = (unsigned)nz * (Ydim * Xdim) + (unsigned)ny * Xdim + (unsigned)nx;
    if (!((g_bitmap[lin >> 5] >> (lin & 31)) & 1u)) return;
    int nb = g_grid[lin];                      // rare (~0.7% of probes)
    int pos = atomicAdd(&g_npairs, 1);
    g_pairs[pos] = make_int2((i << 5) | k, nb);
}

__device__ __forceinline__ void fma2(unsigned long long& acc, float f,
                                     unsigned long long wv) {
    unsigned long long fv2;
    asm("mov.b64 %0, {%1, %1};" : "=l"(fv2) : "f"(f));
    asm("fma.rn.f32x2 %0, %1, %2, %3;" : "=l"(acc) : "l"(fv2), "l"(wv), "l"(acc));
}

// Center matvec: out[i] = feat[i] @ W13. One warp per point (persistent).
// Weights live ENTIRELY in registers (lane owns (cout=lane, cout=lane+32)
// for all 32 cin); feature row read as broadcast LDG.128 (1 wavefront each).
// No probing, no ballots, no smem -> no sync points in the loop.
__global__ void __launch_bounds__(128) center_kernel(
    const float* __restrict__ feat,
    const float* __restrict__ w,
    float* __restrict__ out,
    int n)
{
    int lane   = threadIdx.x & 31;
    int warp_g = (blockIdx.x * blockDim.x + threadIdx.x) >> 5;
    int nwarps = (gridDim.x * blockDim.x) >> 5;

    const float* w13 = w + KCENTER * C_IN * C_OUT;
    unsigned long long wreg[C_IN];
    #pragma unroll
    for (int c = 0; c < C_IN; ++c) {
        float a = w13[c * C_OUT + lane];          // coalesced, L1/L2-hot
        float b = w13[c * C_OUT + lane + 32];
        asm("mov.b64 %0, {%1, %2};" : "=l"(wreg[c]) : "f"(a), "f"(b));
    }

    for (int i = warp_g; i < n; i += nwarps) {
        const float4* frow = (const float4*)(feat + (size_t)i * C_IN);
        unsigned long long acc0, acc1;
        asm("mov.b64 %0, {%1, %1};" : "=l"(acc0) : "f"(0.0f));
        asm("mov.b64 %0, {%1, %1};" : "=l"(acc1) : "f"(0.0f));
        #pragma unroll
        for (int c4 = 0; c4 < C_IN / 4; ++c4) {
            float4 fv = frow[c4];                 // all lanes same addr
            fma2(acc0, fv.x, wreg[c4 * 4 + 0]);
            fma2(acc1, fv.y, wreg[c4 * 4 + 1]);
            fma2(acc0, fv.z, wreg[c4 * 4 + 2]);
            fma2(acc1, fv.w, wreg[c4 * 4 + 3]);
        }
        float a0, a1, b0, b1;
        asm("mov.b64 {%0, %1}, %2;" : "=f"(a0), "=f"(a1) : "l"(acc0));
        asm("mov.b64 {%0, %1}, %2;" : "=f"(b0), "=f"(b1) : "l"(acc1));
        out[(size_t)i * C_OUT + lane]      = a0 + b0;
        out[(size_t)i * C_OUT + lane + 32] = a1 + b1;
    }
}

// Rare neighbor contributions. One warp per TWO pairs per iteration
// (independent chains for latency overlap). Feature rows read as broadcast
// float4 loads (no shuffles); weights coalesced, L1/L2-hot.
__global__ void __launch_bounds__(256) pairs_kernel(
    const float* __restrict__ feat,
    const float* __restrict__ w,
    float* __restrict__ out)
{
    int lane   = threadIdx.x & 31;
    int warp_g = (blockIdx.x * blockDim.x + threadIdx.x) >> 5;
    int nwarps = (gridDim.x * blockDim.x) >> 5;
    int np = g_npairs;

    for (int p = warp_g * 2; p < np; p += nwarps * 2) {
        int2 pr0 = g_pairs[p];
        bool has1 = (p + 1) < np;
        int2 pr1 = has1 ? g_pairs[p + 1] : pr0;

        const float4* f0 = (const float4*)(feat + (size_t)pr0.y * C_IN);
        const float4* f1 = (const float4*)(feat + (size_t)pr1.y * C_IN);
        const float* wk0 = w + (size_t)(pr0.x & 31) * C_IN * C_OUT;
        const float* wk1 = w + (size_t)(pr1.x & 31) * C_IN * C_OUT;

        float a0 = 0.f, a1 = 0.f, b0 = 0.f, b1 = 0.f;
        #pragma unroll
        for (int c4 = 0; c4 < C_IN / 4; ++c4) {
            float4 fv0 = f0[c4];                  // broadcast
            float4 fv1 = f1[c4];
            #pragma unroll
            for (int q = 0; q < 4; ++q) {
                int c = c4 * 4 + q;
                float x0 = (q == 0) ? fv0.x : (q == 1) ? fv0.y : (q == 2) ? fv0.z : fv0.w;
                float x1 = (q == 0) ? fv1.x : (q == 1) ? fv1.y : (q == 2) ? fv1.z : fv1.w;
                a0 += x0 * wk0[c * C_OUT + lane];
                a1 += x0 * wk0[c * C_OUT + lane + 32];
                b0 += x1 * wk1[c * C_OUT + lane];
                b1 += x1 * wk1[c * C_OUT + lane + 32];
            }
        }
        int i0 = pr0.x >> 5;
        atomicAdd(&out[(size_t)i0 * C_OUT + lane],      a0);
        atomicAdd(&out[(size_t)i0 * C_OUT + lane + 32], a1);
        if (has1) {
            int i1 = pr1.x >> 5;
            atomicAdd(&out[(size_t)i1 * C_OUT + lane],      b0);
            atomicAdd(&out[(size_t)i1 * C_OUT + lane + 32], b1);
        }
    }
}

extern "C" void kernel_launch(void* const* d_in, const int* in_sizes, int n_in,
                              void* d_out, int out_size) {
    const float* feat = (const float*)d_in[0];
    const int*   idx  = (const int*)d_in[1];
    const float* w    = (const float*)d_in[2];
    float* out = (float*)d_out;

    int n = in_sizes[0] / C_IN;

    clear_bitmap_kernel<<<(NWORDS / 4 + 255) / 256, 256>>>();
    scatter_kernel<<<(n + 255) / 256, 256>>>(idx, n);
    probe_kernel<<<(n * KVOL + 255) / 256, 256>>>(idx, n);
    center_kernel<<<2368, 128>>>(feat, w, out, n);
    pairs_kernel<<<592, 256>>>(feat, w, out);
}

// round 7
// speedup vs baseline: 1.9635x; 1.5923x over previous
#include <cuda_runtime.h>
#include <cstdint>

#define Zdim 41
#define Ydim 1024
#define Xdim 1024
#define NVOX (Zdim * Ydim * Xdim)      // 42,991,616
#define NWORDS (NVOX / 32)             // 1,343,488
#define C_IN 32
#define C_OUT 64
#define KVOL 27
#define KCENTER 13
#define MAXN 300000
#define TILE 64                        // points per tile (64*32 floats = 8 KB)

// Dense index grid: validity gated by g_bitmap (wiped each launch); the grid
// itself is never cleared, so stale entries are never read.
__device__ int      g_grid[NVOX];
__device__ unsigned g_bitmap[NWORDS];
__device__ int      g_npairs;
__device__ int2     g_pairs[MAXN * 8];

__global__ void clear_bitmap_kernel() {
    int i = blockIdx.x * blockDim.x + threadIdx.x;
    if (i == 0) g_npairs = 0;
    if (i * 4 < NWORDS) ((uint4*)g_bitmap)[i] = make_uint4(0, 0, 0, 0);
}

__global__ void scatter_kernel(const int* __restrict__ idx, int n) {
    int i = blockIdx.x * blockDim.x + threadIdx.x;
    if (i >= n) return;
    int4 v = ((const int4*)idx)[i];
    unsigned lin = (unsigned)v.y * (Ydim * Xdim) + (unsigned)v.z * Xdim + (unsigned)v.w;
    g_grid[lin] = i;
    atomicOr(&g_bitmap[lin >> 5], 1u << (lin & 31));
}

// One thread per (point, offset): fully parallel probing, no chains.
__global__ void probe_kernel(const int* __restrict__ idx, int n) {
    int t = blockIdx.x * blockDim.x + threadIdx.x;
    if (t >= n * KVOL) return;
    int i = t / KVOL;
    int k = t - i * KVOL;
    if (k == KCENTER) return;
    int4 v = ((const int4*)idx)[i];
    int nz = v.y + k / 9 - 1;
    int ny = v.z + (k / 3) % 3 - 1;
    int nx = v.w + k % 3 - 1;
    if ((unsigned)nz >= Zdim || (unsigned)ny >= Ydim || (unsigned)nx >= Xdim) return;
    unsigned lin = (unsigned)nz * (Ydim * Xdim) + (unsigned)ny * Xdim + (unsigned)nx;
    if (!((g_bitmap[lin >> 5] >> (lin & 31)) & 1u)) return;
    int nb = g_grid[lin];
    int pos = atomicAdd(&g_npairs, 1);
    g_pairs[pos] = make_int2((i << 5) | k, nb);
}

__device__ __forceinline__ void fma2(unsigned long long& acc, float f,
                                     unsigned long long wv) {
    unsigned long long fv2;
    asm("mov.b64 %0, {%1, %1};" : "=l"(fv2) : "f"(f));
    asm("fma.rn.f32x2 %0, %1, %2, %3;" : "=l"(acc) : "l"(fv2), "l"(wv), "l"(acc));
}

// Center matvec, software-pipelined:
//   prefetch tile t+1 (coalesced LDG.128 -> regs)
//   compute tile t from smem (broadcast LDS.128 + register weights + FFMA2)
//   STS prefetched regs into the other buffer; one barrier per tile.
// The DRAM latency of the prefetch hides under the tile's compute.
__global__ void __launch_bounds__(256) center_kernel(
    const float* __restrict__ feat,
    const float* __restrict__ w,
    float* __restrict__ out,
    int n)
{
    __shared__ float4 sf[2][TILE * (C_IN / 4)];   // 2 x 8 KB

    int tid   = threadIdx.x;
    int lane  = tid & 31;
    int wslot = tid >> 5;

    // Per-lane center weights: wreg[c] = (w13[c][lane], w13[c][lane+32]).
    const float* w13 = w + KCENTER * C_IN * C_OUT;
    unsigned long long wreg[C_IN];
    #pragma unroll
    for (int c = 0; c < C_IN; ++c) {
        float a = w13[c * C_OUT + lane];
        float b = w13[c * C_OUT + lane + 32];
        asm("mov.b64 %0, {%1, %2};" : "=l"(wreg[c]) : "f"(a), "f"(b));
    }

    const float4* featv = (const float4*)feat;
    long maxf4 = (long)n * (C_IN / 4) - 1;       // clamp for partial tiles
    int ntiles = (n + TILE - 1) / TILE;

    int t = blockIdx.x;
    float4 r0, r1;
    if (t < ntiles) {
        long base = (long)t * (TILE * C_IN / 4);
        long i0 = base + tid;       if (i0 > maxf4) i0 = maxf4;
        long i1 = base + tid + 256; if (i1 > maxf4) i1 = maxf4;
        r0 = featv[i0];
        r1 = featv[i1];
    }

    int buf = 0;
    for (; t < ntiles; t += gridDim.x) {
        // stage current tile
        sf[buf][tid]       = r0;
        sf[buf][tid + 256] = r1;
        __syncthreads();

        // prefetch next tile (latency hides under compute below)
        int tn = t + gridDim.x;
        if (tn < ntiles) {
            long base = (long)tn * (TILE * C_IN / 4);
            long i0 = base + tid;       if (i0 > maxf4) i0 = maxf4;
            long i1 = base + tid + 256; if (i1 > maxf4) i1 = maxf4;
            r0 = featv[i0];
            r1 = featv[i1];
        }

        // compute: each warp handles 8 points of the tile
        int p0 = wslot * 8;
        #pragma unroll
        for (int pp = 0; pp < 8; ++pp) {
            int i = t * TILE + p0 + pp;
            if (i >= n) break;
            const float4* frow = &sf[buf][(p0 + pp) * (C_IN / 4)];
            unsigned long long acc0, acc1;
            asm("mov.b64 %0, {%1, %1};" : "=l"(acc0) : "f"(0.0f));
            asm("mov.b64 %0, {%1, %1};" : "=l"(acc1) : "f"(0.0f));
            #pragma unroll
            for (int c4 = 0; c4 < C_IN / 4; ++c4) {
                float4 fv = frow[c4];                // broadcast LDS.128
                fma2(acc0, fv.x, wreg[c4 * 4 + 0]);
                fma2(acc1, fv.y, wreg[c4 * 4 + 1]);
                fma2(acc0, fv.z, wreg[c4 * 4 + 2]);
                fma2(acc1, fv.w, wreg[c4 * 4 + 3]);
            }
            float a0, a1, b0, b1;
            asm("mov.b64 {%0, %1}, %2;" : "=f"(a0), "=f"(a1) : "l"(acc0));
            asm("mov.b64 {%0, %1}, %2;" : "=f"(b0), "=f"(b1) : "l"(acc1));
            out[(size_t)i * C_OUT + lane]      = a0 + b0;
            out[(size_t)i * C_OUT + lane + 32] = a1 + b1;
        }
        __syncthreads();
        buf ^= 1;
    }
}

// Rare neighbor contributions: 2 pairs per warp-iteration for ILP;
// broadcast feature loads, coalesced hot weights, atomicAdd accumulate.
__global__ void __launch_bounds__(256) pairs_kernel(
    const float* __restrict__ feat,
    const float* __restrict__ w,
    float* __restrict__ out)
{
    int lane   = threadIdx.x & 31;
    int warp_g = (blockIdx.x * blockDim.x + threadIdx.x) >> 5;
    int nwarps = (gridDim.x * blockDim.x) >> 5;
    int np = g_npairs;

    for (int p = warp_g * 2; p < np; p += nwarps * 2) {
        int2 pr0 = g_pairs[p];
        bool has1 = (p + 1) < np;
        int2 pr1 = has1 ? g_pairs[p + 1] : pr0;

        const float4* f0 = (const float4*)(feat + (size_t)pr0.y * C_IN);
        const float4* f1 = (const float4*)(feat + (size_t)pr1.y * C_IN);
        const float* wk0 = w + (size_t)(pr0.x & 31) * C_IN * C_OUT;
        const float* wk1 = w + (size_t)(pr1.x & 31) * C_IN * C_OUT;

        float a0 = 0.f, a1 = 0.f, b0 = 0.f, b1 = 0.f;
        #pragma unroll
        for (int c4 = 0; c4 < C_IN / 4; ++c4) {
            float4 fv0 = f0[c4];
            float4 fv1 = f1[c4];
            #pragma unroll
            for (int q = 0; q < 4; ++q) {
                int c = c4 * 4 + q;
                float x0 = (q == 0) ? fv0.x : (q == 1) ? fv0.y : (q == 2) ? fv0.z : fv0.w;
                float x1 = (q == 0) ? fv1.x : (q == 1) ? fv1.y : (q == 2) ? fv1.z : fv1.w;
                a0 += x0 * wk0[c * C_OUT + lane];
                a1 += x0 * wk0[c * C_OUT + lane + 32];
                b0 += x1 * wk1[c * C_OUT + lane];
                b1 += x1 * wk1[c * C_OUT + lane + 32];
            }
        }
        int i0 = pr0.x >> 5;
        atomicAdd(&out[(size_t)i0 * C_OUT + lane],      a0);
        atomicAdd(&out[(size_t)i0 * C_OUT + lane + 32], a1);
        if (has1) {
            int i1 = pr1.x >> 5;
            atomicAdd(&out[(size_t)i1 * C_OUT + lane],      b0);
            atomicAdd(&out[(size_t)i1 * C_OUT + lane + 32], b1);
        }
    }
}

extern "C" void kernel_launch(void* const* d_in, const int* in_sizes, int n_in,
                              void* d_out, int out_size) {
    const float* feat = (const float*)d_in[0];
    const int*   idx  = (const int*)d_in[1];
    const float* w    = (const float*)d_in[2];
    float* out = (float*)d_out;

    int n = in_sizes[0] / C_IN;

    clear_bitmap_kernel<<<(NWORDS / 4 + 255) / 256, 256>>>();
    scatter_kernel<<<(n + 255) / 256, 256>>>(idx, n);
    probe_kernel<<<(n * KVOL + 255) / 256, 256>>>(idx, n);
    center_kernel<<<296, 256>>>(feat, w, out, n);
    pairs_kernel<<<592, 256>>>(feat, w, out);
}

// round 8
// speedup vs baseline: 2.1473x; 1.0936x over previous
#include <cuda_runtime.h>
#include <cstdint>

#define Zdim 41
#define Ydim 1024
#define Xdim 1024
#define NVOX (Zdim * Ydim * Xdim)      // 42,991,616
#define NWORDS (NVOX / 32)             // 1,343,488
#define C_IN 32
#define C_OUT 64
#define KVOL 27
#define KCENTER 13
#define MAXN 300000
#define TILE 64

// Dense index grid: validity gated by g_bitmap (wiped each launch); the grid
// itself is never cleared, so stale entries are never read.
__device__ int      g_grid[NVOX];
__device__ unsigned g_bitmap[NWORDS];
__device__ int      g_npairs;
__device__ int2     g_pairs[MAXN * 8];

__global__ void clear_bitmap_kernel() {
    int i = blockIdx.x * blockDim.x + threadIdx.x;
    if (i == 0) g_npairs = 0;
    if (i * 4 < NWORDS) ((uint4*)g_bitmap)[i] = make_uint4(0, 0, 0, 0);
}

__global__ void scatter_kernel(const int* __restrict__ idx, int n) {
    int i = blockIdx.x * blockDim.x + threadIdx.x;
    if (i >= n) return;
    int4 v = ((const int4*)idx)[i];
    unsigned lin = (unsigned)v.y * (Ydim * Xdim) + (unsigned)v.z * Xdim + (unsigned)v.w;
    g_grid[lin] = i;
    atomicOr(&g_bitmap[lin >> 5], 1u << (lin & 31));
}

// Symmetric probing: only offsets k<13 are probed; each hit emits the pair
// AND its mirror (j at offset k from i  <=>  i at offset 26-k from j).
// The 13 offsets collapse into 5 groups -- 4 (dz,dy) x-triplets + 1 single
// (dz=0,dy=0,dx=-1) -- each needing ONE bitmap word (row base is 32-aligned
// since X=1024; only x&31 in {0,31} needs a second word).
__global__ void probe_kernel(const int* __restrict__ idx, int n) {
    int t = blockIdx.x * blockDim.x + threadIdx.x;
    if (t >= n * 5) return;
    int i = t / 5;
    int g = t - i * 5;
    int4 v = ((const int4*)idx)[i];

    int dz = (g < 3) ? -1 : 0;           // groups: (-1,-1) (-1,0) (-1,1) (0,-1) (0,0)
    int dy = (g < 3) ? (g - 1) : (g - 4);
    int nz = v.y + dz;
    int ny = v.z + dy;
    if ((unsigned)nz >= Zdim || (unsigned)ny >= Ydim) return;

    unsigned rowbase = ((unsigned)nz * Ydim + (unsigned)ny) * Xdim;
    int x = v.w;
    unsigned lin0 = rowbase + (unsigned)x;
    unsigned w0   = g_bitmap[lin0 >> 5];

    int kbase = (dz + 1) * 9 + (dy + 1) * 3;     // + (dx+1) gives k (all < 13)
    int dxhi = (g == 4) ? -1 : 1;                // group 4 probes dx=-1 only

    #pragma unroll
    for (int dx = -1; dx <= 1; ++dx) {
        if (dx > dxhi) break;
        int nx = x + dx;
        if ((unsigned)nx >= Xdim) continue;
        unsigned lin = rowbase + (unsigned)nx;
        unsigned word = ((lin >> 5) == (lin0 >> 5)) ? w0 : g_bitmap[lin >> 5];
        if ((word >> (lin & 31)) & 1u) {
            int nb = g_grid[lin];                // rare
            int k = kbase + dx + 1;
            int pos = atomicAdd(&g_npairs, 2);
            g_pairs[pos]     = make_int2((i  << 5) | k,        nb);
            g_pairs[pos + 1] = make_int2((nb << 5) | (26 - k), i);
        }
    }
}

__device__ __forceinline__ void fma2(unsigned long long& acc, float f,
                                     unsigned long long wv) {
    unsigned long long fv2;
    asm("mov.b64 %0, {%1, %1};" : "=l"(fv2) : "f"(f));
    asm("fma.rn.f32x2 %0, %1, %2, %3;" : "=l"(acc) : "l"(fv2), "l"(wv), "l"(acc));
}

// Center matvec, software-pipelined (prefetch next tile -> regs while
// computing current tile from smem). Weights in registers; 4 independent
// FFMA2 accumulator chains per point for ILP.
__global__ void __launch_bounds__(256) center_kernel(
    const float* __restrict__ feat,
    const float* __restrict__ w,
    float* __restrict__ out,
    int n)
{
    __shared__ float4 sf[2][TILE * (C_IN / 4)];

    int tid   = threadIdx.x;
    int lane  = tid & 31;
    int wslot = tid >> 5;

    const float* w13 = w + KCENTER * C_IN * C_OUT;
    unsigned long long wreg[C_IN];
    #pragma unroll
    for (int c = 0; c < C_IN; ++c) {
        float a = w13[c * C_OUT + lane];
        float b = w13[c * C_OUT + lane + 32];
        asm("mov.b64 %0, {%1, %2};" : "=l"(wreg[c]) : "f"(a), "f"(b));
    }

    const float4* featv = (const float4*)feat;
    long maxf4 = (long)n * (C_IN / 4) - 1;
    int ntiles = (n + TILE - 1) / TILE;

    int t = blockIdx.x;
    float4 r0, r1;
    if (t < ntiles) {
        long base = (long)t * (TILE * C_IN / 4);
        long i0 = base + tid;       if (i0 > maxf4) i0 = maxf4;
        long i1 = base + tid + 256; if (i1 > maxf4) i1 = maxf4;
        r0 = featv[i0];
        r1 = featv[i1];
    }

    int buf = 0;
    for (; t < ntiles; t += gridDim.x) {
        sf[buf][tid]       = r0;
        sf[buf][tid + 256] = r1;
        __syncthreads();

        int tn = t + gridDim.x;
        if (tn < ntiles) {
            long base = (long)tn * (TILE * C_IN / 4);
            long i0 = base + tid;       if (i0 > maxf4) i0 = maxf4;
            long i1 = base + tid + 256; if (i1 > maxf4) i1 = maxf4;
            r0 = featv[i0];
            r1 = featv[i1];
        }

        int p0 = wslot * 8;
        #pragma unroll
        for (int pp = 0; pp < 8; ++pp) {
            int i = t * TILE + p0 + pp;
            if (i >= n) break;
            const float4* frow = &sf[buf][(p0 + pp) * (C_IN / 4)];
            unsigned long long acc0, acc1, acc2, acc3;
            asm("mov.b64 %0, {%1, %1};" : "=l"(acc0) : "f"(0.0f));
            asm("mov.b64 %0, {%1, %1};" : "=l"(acc1) : "f"(0.0f));
            asm("mov.b64 %0, {%1, %1};" : "=l"(acc2) : "f"(0.0f));
            asm("mov.b64 %0, {%1, %1};" : "=l"(acc3) : "f"(0.0f));
            #pragma unroll
            for (int c4 = 0; c4 < C_IN / 4; ++c4) {
                float4 fv = frow[c4];                // broadcast LDS.128
                fma2(acc0, fv.x, wreg[c4 * 4 + 0]);
                fma2(acc1, fv.y, wreg[c4 * 4 + 1]);
                fma2(acc2, fv.z, wreg[c4 * 4 + 2]);
                fma2(acc3, fv.w, wreg[c4 * 4 + 3]);
            }
            float a0, a1, b0, b1, c0, c1, d0, d1;
            asm("mov.b64 {%0, %1}, %2;" : "=f"(a0), "=f"(a1) : "l"(acc0));
            asm("mov.b64 {%0, %1}, %2;" : "=f"(b0), "=f"(b1) : "l"(acc1));
            asm("mov.b64 {%0, %1}, %2;" : "=f"(c0), "=f"(c1) : "l"(acc2));
            asm("mov.b64 {%0, %1}, %2;" : "=f"(d0), "=f"(d1) : "l"(acc3));
            out[(size_t)i * C_OUT + lane]      = (a0 + b0) + (c0 + d0);
            out[(size_t)i * C_OUT + lane + 32] = (a1 + b1) + (c1 + d1);
        }
        __syncthreads();
        buf ^= 1;
    }
}

// Rare neighbor contributions: 2 pairs per warp-iteration for ILP;
// broadcast feature loads, hot coalesced weights, atomicAdd accumulate.
__global__ void __launch_bounds__(256) pairs_kernel(
    const float* __restrict__ feat,
    const float* __restrict__ w,
    float* __restrict__ out)
{
    int lane   = threadIdx.x & 31;
    int warp_g = (blockIdx.x * blockDim.x + threadIdx.x) >> 5;
    int nwarps = (gridDim.x * blockDim.x) >> 5;
    int np = g_npairs;

    for (int p = warp_g * 2; p < np; p += nwarps * 2) {
        int2 pr0 = g_pairs[p];
        bool has1 = (p + 1) < np;
        int2 pr1 = has1 ? g_pairs[p + 1] : pr0;

        const float4* f0 = (const float4*)(feat + (size_t)pr0.y * C_IN);
        const float4* f1 = (const float4*)(feat + (size_t)pr1.y * C_IN);
        const float* wk0 = w + (size_t)(pr0.x & 31) * C_IN * C_OUT;
        const float* wk1 = w + (size_t)(pr1.x & 31) * C_IN * C_OUT;

        float a0 = 0.f, a1 = 0.f, b0 = 0.f, b1 = 0.f;
        #pragma unroll
        for (int c4 = 0; c4 < C_IN / 4; ++c4) {
            float4 fv0 = f0[c4];
            float4 fv1 = f1[c4];
            #pragma unroll
            for (int q = 0; q < 4; ++q) {
                int c = c4 * 4 + q;
                float x0 = (q == 0) ? fv0.x : (q == 1) ? fv0.y : (q == 2) ? fv0.z : fv0.w;
                float x1 = (q == 0) ? fv1.x : (q == 1) ? fv1.y : (q == 2) ? fv1.z : fv1.w;
                a0 += x0 * wk0[c * C_OUT + lane];
                a1 += x0 * wk0[c * C_OUT + lane + 32];
                b0 += x1 * wk1[c * C_OUT + lane];
                b1 += x1 * wk1[c * C_OUT + lane + 32];
            }
        }
        int i0 = pr0.x >> 5;
        atomicAdd(&out[(size_t)i0 * C_OUT + lane],      a0);
        atomicAdd(&out[(size_t)i0 * C_OUT + lane + 32], a1);
        if (has1) {
            int i1 = pr1.x >> 5;
            atomicAdd(&out[(size_t)i1 * C_OUT + lane],      b0);
            atomicAdd(&out[(size_t)i1 * C_OUT + lane + 32], b1);
        }
    }
}

extern "C" void kernel_launch(void* const* d_in, const int* in_sizes, int n_in,
                              void* d_out, int out_size) {
    const float* feat = (const float*)d_in[0];
    const int*   idx  = (const int*)d_in[1];
    const float* w    = (const float*)d_in[2];
    float* out = (float*)d_out;

    int n = in_sizes[0] / C_IN;

    clear_bitmap_kernel<<<(NWORDS / 4 + 255) / 256, 256>>>();
    scatter_kernel<<<(n + 255) / 256, 256>>>(idx, n);
    probe_kernel<<<(n * 5 + 255) / 256, 256>>>(idx, n);
    center_kernel<<<296, 256>>>(feat, w, out, n);
    pairs_kernel<<<592, 256>>>(feat, w, out);
}